// round 5
// baseline (speedup 1.0000x reference)
#include <cuda_runtime.h>
#include <cuda_bf16.h>
#include <cstdint>

// AtomicComposition: counts[s][k] = #atoms in structure s with species == all_species[k]
// species:            d_in[2]  int32  [n_atoms]
// structure_offsets:  d_in[8]  int32 OR int64 [n_structures] (CSR starts) -- dtype probed on device
// all_species:        d_in[9]  int32  [n_species]
// out: float32 [n_structures, n_species]

__device__ __forceinline__ bool probe_is64(const void* offs, int n_structures,
                                           long long n_atoms) {
    // Genuine int64 offsets: element [1] is a small valid offset.
    // int32 data misread as int64: (a[2] | a[3]<<32), astronomically large.
    if (n_structures <= 1) return true;
    const long long probe = ((const long long*)offs)[1];
    return (probe >= 0 && probe <= n_atoms);
}

__device__ __forceinline__ int load_offset32(const void* offs, int i, bool is64) {
    if (is64) return (int)((const long long*)offs)[i];
    return ((const int*)offs)[i];
}

// One warp handles G consecutive structures. 256 threads = 8 warps per CTA.
// All index math in int32 (valid while n_atoms < 2^31).
template <int NS, int G>
__global__ __launch_bounds__(256) void atomic_composition_warpG(
    const int* __restrict__ species,
    const void* __restrict__ offsets,
    const int* __restrict__ all_species,
    float* __restrict__ out,
    int n_structures,
    int n_atoms)
{
    const int gwarp = (blockIdx.x * blockDim.x + threadIdx.x) >> 5;
    const int lid   = threadIdx.x & 31;
    const int s0    = gwarp * G;
    if (s0 >= n_structures) return;

    const bool is64 = probe_is64(offsets, n_structures, (long long)n_atoms);

    // Lane-parallel load of offsets[s0 .. s0+G] (G+1 values), distributed by shfl.
    int my_off = 0;
    if (lid <= G) {
        const int idx = s0 + lid;
        my_off = (idx < n_structures) ? load_offset32(offsets, idx, is64) : n_atoms;
    }

    int sp[NS];
#pragma unroll
    for (int k = 0; k < NS; ++k) sp[k] = __ldg(&all_species[k]);

#pragma unroll
    for (int g = 0; g < G; ++g) {
        const int s = s0 + g;
        if (s >= n_structures) break;

        const int start = __shfl_sync(0xFFFFFFFFu, my_off, g);
        const int end   = __shfl_sync(0xFFFFFFFFu, my_off, g + 1);

        int cnt[NS];
#pragma unroll
        for (int k = 0; k < NS; ++k) cnt[k] = 0;

        const int n = end - start;

        if (((start & 3) | (n & 3)) == 0) {
            // fully vectorized: no scalar tail
            const int4* __restrict__ base = reinterpret_cast<const int4*>(species + start);
            const int nq = n >> 2;
            int q = lid;
            for (; q + 32 < nq; q += 64) {
                const int4 a = base[q];
                const int4 b = base[q + 32];
#pragma unroll
                for (int k = 0; k < NS; ++k) {
                    cnt[k] += (a.x == sp[k]) + (a.y == sp[k]) + (a.z == sp[k]) + (a.w == sp[k]);
                    cnt[k] += (b.x == sp[k]) + (b.y == sp[k]) + (b.z == sp[k]) + (b.w == sp[k]);
                }
            }
            for (; q < nq; q += 32) {
                const int4 a = base[q];
#pragma unroll
                for (int k = 0; k < NS; ++k) {
                    cnt[k] += (a.x == sp[k]) + (a.y == sp[k]) + (a.z == sp[k]) + (a.w == sp[k]);
                }
            }
        } else {
            for (int j = start + lid; j < end; j += 32) {
                const int z = species[j];
#pragma unroll
                for (int k = 0; k < NS; ++k) cnt[k] += (z == sp[k]);
            }
        }

#pragma unroll
        for (int k = 0; k < NS; ++k) cnt[k] = __reduce_add_sync(0xFFFFFFFFu, cnt[k]);

        if (lid == 0) {
            float* o = out + s * NS;
#pragma unroll
            for (int k = 0; k < NS; ++k) o[k] = (float)cnt[k];
        }
    }
}

// Fallback for arbitrary n_species (shared-memory counters, CTA per structure)
__global__ __launch_bounds__(64) void atomic_composition_generic(
    const int* __restrict__ species,
    const void* __restrict__ offsets,
    const int* __restrict__ all_species,
    float* __restrict__ out,
    int n_structures,
    long long n_atoms,
    int n_species)
{
    extern __shared__ int shc[];
    const int s   = blockIdx.x;
    const int tid = threadIdx.x;
    for (int k = tid; k < n_species; k += 64) shc[k] = 0;
    __syncthreads();

    const bool is64 = probe_is64(offsets, n_structures, n_atoms);
    const long long start = is64 ? ((const long long*)offsets)[s]
                                 : (long long)((const int*)offsets)[s];
    long long end = n_atoms;
    if (s + 1 < n_structures)
        end = is64 ? ((const long long*)offsets)[s + 1]
                   : (long long)((const int*)offsets)[s + 1];

    for (long long j = start + tid; j < end; j += 64) {
        const int z = species[j];
        for (int k = 0; k < n_species; ++k)
            if (z == __ldg(&all_species[k])) atomicAdd(&shc[k], 1);
    }
    __syncthreads();
    for (int k = tid; k < n_species; k += 64)
        out[(long long)s * n_species + k] = (float)shc[k];
}

extern "C" void kernel_launch(void* const* d_in, const int* in_sizes, int n_in,
                              void* d_out, int out_size)
{
    const int*  species     = (const int*)d_in[2];
    const void* offsets     = d_in[8];
    const int*  all_species = (const int*)d_in[9];
    float*      out         = (float*)d_out;

    const long long n_atoms      = (long long)in_sizes[2];
    const int       n_structures = in_sizes[8];
    const int       n_species    = in_sizes[9];

    if (n_species == 5 && n_atoms < 0x7FFFFFFFLL) {
        constexpr int G = 4;                          // structures per warp
        const int warps = (n_structures + G - 1) / G;
        const int ctas  = (warps * 32 + 255) / 256;   // 8 warps per CTA
        atomic_composition_warpG<5, G><<<ctas, 256>>>(
            species, offsets, all_species, out, n_structures, (int)n_atoms);
    } else {
        atomic_composition_generic<<<n_structures, 64, n_species * sizeof(int)>>>(
            species, offsets, all_species, out, n_structures, n_atoms, n_species);
    }
}

// round 6
// speedup vs baseline: 1.0737x; 1.0737x over previous
#include <cuda_runtime.h>
#include <cuda_bf16.h>
#include <cstdint>

// AtomicComposition: counts[s][k] = #atoms in structure s with species == all_species[k]
// species:            d_in[2]  int32  [n_atoms]
// structure_offsets:  d_in[8]  int32 OR int64 [n_structures] (CSR starts) -- dtype probed on device
// all_species:        d_in[9]  int32  [n_species]
// out: float32 [n_structures, n_species]

__device__ __forceinline__ bool probe_is64(const void* offs, int n_structures,
                                           long long n_atoms) {
    // Genuine int64 offsets: element [1] is a small valid offset.
    // int32 data misread as int64: (a[2] | a[3]<<32), astronomically large.
    if (n_structures <= 1) return true;
    const long long probe = ((const long long*)offs)[1];
    return (probe >= 0 && probe <= n_atoms);
}

__device__ __forceinline__ int load_offset32(const void* offs, int i, bool is64) {
    if (is64) return (int)((const long long*)offs)[i];
    return ((const int*)offs)[i];
}

// NS = 5 specialized kernel. One warp handles 4 consecutive structures.
// Fast path (uniform 256-atom contiguous structures): 8 front-batched LDG.128
// per thread (MLP=8), packed dual-REDUX reduction.
__global__ __launch_bounds__(256) void atomic_composition_g4(
    const int* __restrict__ species,
    const void* __restrict__ offsets,
    const int* __restrict__ all_species,
    float* __restrict__ out,
    int n_structures,
    int n_atoms)
{
    const int gwarp = (blockIdx.x * blockDim.x + threadIdx.x) >> 5;
    const int lid   = threadIdx.x & 31;
    const int s0    = gwarp * 4;
    if (s0 >= n_structures) return;

    const bool is64 = probe_is64(offsets, n_structures, (long long)n_atoms);

    // offsets[s0 .. s0+4] loaded lane-parallel, distributed by shfl
    int my_off = n_atoms;
    if (lid <= 4) {
        const int idx = s0 + lid;
        my_off = (idx < n_structures) ? load_offset32(offsets, idx, is64) : n_atoms;
    }
    const int start0 = __shfl_sync(0xFFFFFFFFu, my_off, 0);

    int sp0 = __ldg(&all_species[0]);
    int sp1 = __ldg(&all_species[1]);
    int sp2 = __ldg(&all_species[2]);
    int sp3 = __ldg(&all_species[3]);
    int sp4 = __ldg(&all_species[4]);

    // uniform fast path: 4 contiguous structures of exactly 256 atoms
    const bool uni = __all_sync(0xFFFFFFFFu,
                                (lid > 4) || (my_off == start0 + lid * 256));

    if (uni && (s0 + 4 <= n_structures) && ((start0 & 3) == 0)) {
        const int4* __restrict__ B = reinterpret_cast<const int4*>(species + start0);
        // 8 independent streaming LDG.128: warp covers 1024 atoms
        int4 A[8];
#pragma unroll
        for (int i = 0; i < 8; ++i) A[i] = __ldcs(&B[i * 32 + lid]);

#pragma unroll
        for (int g = 0; g < 4; ++g) {
            const int4 u = A[2 * g];
            const int4 v = A[2 * g + 1];
            int c0 = (u.x==sp0)+(u.y==sp0)+(u.z==sp0)+(u.w==sp0)
                   + (v.x==sp0)+(v.y==sp0)+(v.z==sp0)+(v.w==sp0);
            int c1 = (u.x==sp1)+(u.y==sp1)+(u.z==sp1)+(u.w==sp1)
                   + (v.x==sp1)+(v.y==sp1)+(v.z==sp1)+(v.w==sp1);
            int c2 = (u.x==sp2)+(u.y==sp2)+(u.z==sp2)+(u.w==sp2)
                   + (v.x==sp2)+(v.y==sp2)+(v.z==sp2)+(v.w==sp2);
            int c3 = (u.x==sp3)+(u.y==sp3)+(u.z==sp3)+(u.w==sp3)
                   + (v.x==sp3)+(v.y==sp3)+(v.z==sp3)+(v.w==sp3);
            int c4 = (u.x==sp4)+(u.y==sp4)+(u.z==sp4)+(u.w==sp4)
                   + (v.x==sp4)+(v.y==sp4)+(v.z==sp4)+(v.w==sp4);

            // per-lane counts <= 8; warp sums <= 256 -> 10-bit fields safe
            int pA = c0 | (c1 << 10) | (c2 << 20);
            int pB = c3 | (c4 << 10);
            pA = __reduce_add_sync(0xFFFFFFFFu, pA);
            pB = __reduce_add_sync(0xFFFFFFFFu, pB);

            if (lid == 0) {
                float* o = out + (s0 + g) * 5;
                o[0] = (float)(pA & 1023);
                o[1] = (float)((pA >> 10) & 1023);
                o[2] = (float)((pA >> 20) & 1023);
                o[3] = (float)(pB & 1023);
                o[4] = (float)((pB >> 10) & 1023);
            }
        }
        return;
    }

    // general fallback: per-structure loop (any sizes/alignment)
    for (int g = 0; g < 4; ++g) {
        const int s = s0 + g;
        if (s >= n_structures) break;
        const int start = __shfl_sync(0xFFFFFFFFu, my_off, g);
        const int end   = __shfl_sync(0xFFFFFFFFu, my_off, g + 1);

        int c0 = 0, c1 = 0, c2 = 0, c3 = 0, c4 = 0;
        for (int j = start + lid; j < end; j += 32) {
            const int z = species[j];
            c0 += (z == sp0); c1 += (z == sp1); c2 += (z == sp2);
            c3 += (z == sp3); c4 += (z == sp4);
        }
        c0 = __reduce_add_sync(0xFFFFFFFFu, c0);
        c1 = __reduce_add_sync(0xFFFFFFFFu, c1);
        c2 = __reduce_add_sync(0xFFFFFFFFu, c2);
        c3 = __reduce_add_sync(0xFFFFFFFFu, c3);
        c4 = __reduce_add_sync(0xFFFFFFFFu, c4);
        if (lid == 0) {
            float* o = out + s * 5;
            o[0] = (float)c0; o[1] = (float)c1; o[2] = (float)c2;
            o[3] = (float)c3; o[4] = (float)c4;
        }
    }
}

// Fallback for arbitrary n_species (shared-memory counters, CTA per structure)
__global__ __launch_bounds__(64) void atomic_composition_generic(
    const int* __restrict__ species,
    const void* __restrict__ offsets,
    const int* __restrict__ all_species,
    float* __restrict__ out,
    int n_structures,
    long long n_atoms,
    int n_species)
{
    extern __shared__ int shc[];
    const int s   = blockIdx.x;
    const int tid = threadIdx.x;
    for (int k = tid; k < n_species; k += 64) shc[k] = 0;
    __syncthreads();

    const bool is64 = probe_is64(offsets, n_structures, n_atoms);
    const long long start = is64 ? ((const long long*)offsets)[s]
                                 : (long long)((const int*)offsets)[s];
    long long end = n_atoms;
    if (s + 1 < n_structures)
        end = is64 ? ((const long long*)offsets)[s + 1]
                   : (long long)((const int*)offsets)[s + 1];

    for (long long j = start + tid; j < end; j += 64) {
        const int z = species[j];
        for (int k = 0; k < n_species; ++k)
            if (z == __ldg(&all_species[k])) atomicAdd(&shc[k], 1);
    }
    __syncthreads();
    for (int k = tid; k < n_species; k += 64)
        out[(long long)s * n_species + k] = (float)shc[k];
}

extern "C" void kernel_launch(void* const* d_in, const int* in_sizes, int n_in,
                              void* d_out, int out_size)
{
    const int*  species     = (const int*)d_in[2];
    const void* offsets     = d_in[8];
    const int*  all_species = (const int*)d_in[9];
    float*      out         = (float*)d_out;

    const long long n_atoms      = (long long)in_sizes[2];
    const int       n_structures = in_sizes[8];
    const int       n_species    = in_sizes[9];

    if (n_species == 5 && n_atoms < 0x7FFFFFFFLL) {
        const int warps = (n_structures + 3) / 4;
        const int ctas  = (warps * 32 + 255) / 256;   // 8 warps per CTA
        atomic_composition_g4<<<ctas, 256>>>(
            species, offsets, all_species, out, n_structures, (int)n_atoms);
    } else {
        atomic_composition_generic<<<n_structures, 64, n_species * sizeof(int)>>>(
            species, offsets, all_species, out, n_structures, n_atoms, n_species);
    }
}

// round 7
// speedup vs baseline: 1.2143x; 1.1310x over previous
#include <cuda_runtime.h>
#include <cuda_bf16.h>
#include <cstdint>

// AtomicComposition: counts[s][k] = #atoms in structure s with species == all_species[k]
// species:            d_in[2]  int32  [n_atoms]
// structure_offsets:  d_in[8]  int32 OR int64 [n_structures] (CSR starts) -- dtype probed on device
// all_species:        d_in[9]  int32  [n_species]
// out: float32 [n_structures, n_species]

__device__ __forceinline__ bool probe_is64(const void* offs, int n_structures,
                                           long long n_atoms) {
    // Genuine int64 offsets: element [1] is a small valid offset.
    // int32 data misread as int64: (a[2] | a[3]<<32), astronomically large.
    if (n_structures <= 1) return true;
    const long long probe = ((const long long*)offs)[1];
    return (probe >= 0 && probe <= n_atoms);
}

__device__ __forceinline__ int load_offset32(const void* offs, int i, bool is64) {
    if (is64) return (int)((const long long*)offs)[i];
    return ((const int*)offs)[i];
}

// NS=5 kernel, one warp per 4 consecutive structures.
// Fast path (uniform 256-atom contiguous): 8 front-batched LDG.128 (MLP=8),
// shared packed-LUT (5 counters in 6-bit fields of one word), 2 REDUX/structure.
__global__ __launch_bounds__(256) void atomic_composition_lut(
    const int* __restrict__ species,
    const void* __restrict__ offsets,
    const int* __restrict__ all_species,
    float* __restrict__ out,
    int n_structures,
    int n_atoms)
{
    __shared__ int lut[128];   // lut[z] = sum_k (z==sp[k]) << (6k)

    const int tid = threadIdx.x;
    const int sp0 = __ldg(&all_species[0]);
    const int sp1 = __ldg(&all_species[1]);
    const int sp2 = __ldg(&all_species[2]);
    const int sp3 = __ldg(&all_species[3]);
    const int sp4 = __ldg(&all_species[4]);

    if (tid < 128) {
        const int z = tid;
        lut[tid] = (int)(z == sp0)
                 | ((int)(z == sp1) << 6)
                 | ((int)(z == sp2) << 12)
                 | ((int)(z == sp3) << 18)
                 | ((int)(z == sp4) << 24);
    }
    __syncthreads();

    const int gwarp = (blockIdx.x * blockDim.x + tid) >> 5;
    const int lid   = tid & 31;
    const int s0    = gwarp * 4;
    if (s0 >= n_structures) return;

    const bool is64 = probe_is64(offsets, n_structures, (long long)n_atoms);

    // offsets[s0 .. s0+4] loaded lane-parallel, distributed by shfl
    int my_off = n_atoms;
    if (lid <= 4) {
        const int idx = s0 + lid;
        my_off = (idx < n_structures) ? load_offset32(offsets, idx, is64) : n_atoms;
    }
    const int start0 = __shfl_sync(0xFFFFFFFFu, my_off, 0);

    // uniform fast path: 4 contiguous structures of exactly 256 atoms each
    const bool uni = __all_sync(0xFFFFFFFFu,
                                (lid > 4) || (my_off == start0 + lid * 256));

    if (uni && (s0 + 4 <= n_structures) && ((start0 & 3) == 0)) {
        const int4* __restrict__ B = reinterpret_cast<const int4*>(species + start0);
        int4 A[8];                     // 8 independent streaming LDG.128 (MLP=8)
#pragma unroll
        for (int i = 0; i < 8; ++i) A[i] = __ldcs(&B[i * 32 + lid]);

#pragma unroll
        for (int g = 0; g < 4; ++g) {
            const int4 u = A[2 * g];
            const int4 v = A[2 * g + 1];
            // clamp matches reference's clip(z,0,127); per-field count <= 8 < 64
            int acc;
            acc  = lut[min((unsigned)u.x, 127u)];
            acc += lut[min((unsigned)u.y, 127u)];
            acc += lut[min((unsigned)u.z, 127u)];
            acc += lut[min((unsigned)u.w, 127u)];
            acc += lut[min((unsigned)v.x, 127u)];
            acc += lut[min((unsigned)v.y, 127u)];
            acc += lut[min((unsigned)v.z, 127u)];
            acc += lut[min((unsigned)v.w, 127u)];

            // repack 6-bit fields into two 10-bit-field words (warp sums <= 256)
            int pA = (acc & 63) | (((acc >> 6) & 63) << 10) | (((acc >> 12) & 63) << 20);
            int pB = ((acc >> 18) & 63) | (((acc >> 24) & 63) << 10);
            pA = __reduce_add_sync(0xFFFFFFFFu, pA);
            pB = __reduce_add_sync(0xFFFFFFFFu, pB);

            // lanes 0..4 each store one output value
            const int word = (lid < 3) ? pA : pB;
            const int sh   = (lid < 3) ? (10 * lid) : (10 * (lid - 3));
            if (lid < 5)
                out[(s0 + g) * 5 + lid] = (float)((word >> sh) & 1023);
        }
        return;
    }

    // general fallback: per-structure loop (any sizes/alignment)
    for (int g = 0; g < 4; ++g) {
        const int s = s0 + g;
        if (s >= n_structures) break;
        const int start = __shfl_sync(0xFFFFFFFFu, my_off, g);
        const int end   = __shfl_sync(0xFFFFFFFFu, my_off, g + 1);

        int c0 = 0, c1 = 0, c2 = 0, c3 = 0, c4 = 0;
        for (int j = start + lid; j < end; j += 32) {
            const int z = species[j];
            c0 += (z == sp0); c1 += (z == sp1); c2 += (z == sp2);
            c3 += (z == sp3); c4 += (z == sp4);
        }
        c0 = __reduce_add_sync(0xFFFFFFFFu, c0);
        c1 = __reduce_add_sync(0xFFFFFFFFu, c1);
        c2 = __reduce_add_sync(0xFFFFFFFFu, c2);
        c3 = __reduce_add_sync(0xFFFFFFFFu, c3);
        c4 = __reduce_add_sync(0xFFFFFFFFu, c4);
        if (lid == 0) {
            float* o = out + s * 5;
            o[0] = (float)c0; o[1] = (float)c1; o[2] = (float)c2;
            o[3] = (float)c3; o[4] = (float)c4;
        }
    }
}

// Fallback for arbitrary n_species (shared-memory counters, CTA per structure)
__global__ __launch_bounds__(64) void atomic_composition_generic(
    const int* __restrict__ species,
    const void* __restrict__ offsets,
    const int* __restrict__ all_species,
    float* __restrict__ out,
    int n_structures,
    long long n_atoms,
    int n_species)
{
    extern __shared__ int shc[];
    const int s   = blockIdx.x;
    const int tid = threadIdx.x;
    for (int k = tid; k < n_species; k += 64) shc[k] = 0;
    __syncthreads();

    const bool is64 = probe_is64(offsets, n_structures, n_atoms);
    const long long start = is64 ? ((const long long*)offsets)[s]
                                 : (long long)((const int*)offsets)[s];
    long long end = n_atoms;
    if (s + 1 < n_structures)
        end = is64 ? ((const long long*)offsets)[s + 1]
                   : (long long)((const int*)offsets)[s + 1];

    for (long long j = start + tid; j < end; j += 64) {
        const int z = species[j];
        for (int k = 0; k < n_species; ++k)
            if (z == __ldg(&all_species[k])) atomicAdd(&shc[k], 1);
    }
    __syncthreads();
    for (int k = tid; k < n_species; k += 64)
        out[(long long)s * n_species + k] = (float)shc[k];
}

extern "C" void kernel_launch(void* const* d_in, const int* in_sizes, int n_in,
                              void* d_out, int out_size)
{
    const int*  species     = (const int*)d_in[2];
    const void* offsets     = d_in[8];
    const int*  all_species = (const int*)d_in[9];
    float*      out         = (float*)d_out;

    const long long n_atoms      = (long long)in_sizes[2];
    const int       n_structures = in_sizes[8];
    const int       n_species    = in_sizes[9];

    if (n_species == 5 && n_atoms < 0x7FFFFFFFLL) {
        const int warps = (n_structures + 3) / 4;
        const int ctas  = (warps * 32 + 255) / 256;   // 8 warps per CTA
        atomic_composition_lut<<<ctas, 256>>>(
            species, offsets, all_species, out, n_structures, (int)n_atoms);
    } else {
        atomic_composition_generic<<<n_structures, 64, n_species * sizeof(int)>>>(
            species, offsets, all_species, out, n_structures, n_atoms, n_species);
    }
}